// round 12
// baseline (speedup 1.0000x reference)
#include <cuda_runtime.h>
#include <math.h>
#include <stdint.h>

#define TT 512
#define BB 128
#define HH 256
#define AA 18
#define BH (BB*HH)
#define NCTA 128

#define OFF_BASE 1179648u
#define OFF_ACT  1245184u
#define OFF_HT   1310720u
#define OFF_CT   1376256u

typedef unsigned long long ull;

static __device__ __align__(16) float g_core[(size_t)TT*BH];  // layer-1 h per step
static __device__ __align__(16) float g_h0buf[2][BH];         // layer-0 h ping-pong
static __device__ __align__(16) float g_nd[TT*BB];            // float not-done mask
static __device__ __align__(128) unsigned g_flags[NCTA];      // per-CTA arrival flags
static __device__ unsigned g_epoch;
static __device__ int g_mode;

// ---------------- packed f32x2 + sync helpers ----------------
__device__ __forceinline__ ull ffma2(ull a, ull b, ull c){
    ull d;
    asm("fma.rn.f32x2 %0,%1,%2,%3;" : "=l"(d) : "l"(a), "l"(b), "l"(c));
    return d;
}
__device__ __forceinline__ float hsum2(ull v){
    float lo, hi;
    asm("mov.b64 {%0,%1},%2;" : "=f"(lo), "=f"(hi) : "l"(v));
    return lo + hi;
}
__device__ __forceinline__ ull pack2(float lo, float hi){
    ull r;
    asm("mov.b64 %0,{%1,%2};" : "=l"(r) : "f"(lo), "f"(hi));
    return r;
}
__device__ __forceinline__ float sigf(float x){ return 1.0f/(1.0f+__expf(-x)); }
__device__ __forceinline__ float tanhe(float x){ return 1.0f - 2.0f/(__expf(2.0f*x)+1.0f); }

__device__ __forceinline__ unsigned ld_acq(const unsigned* p){
    unsigned v;
    asm volatile("ld.acquire.gpu.u32 %0,[%1];" : "=r"(v) : "l"(p));
    return v;
}
__device__ __forceinline__ void st_rel(unsigned* p, unsigned v){
    asm volatile("st.release.gpu.u32 [%0],%1;" :: "l"(p), "r"(v));
}

// Grid barrier with per-CTA flag words: zero atomic-ALU contention.
__device__ __forceinline__ void gsync(unsigned target, int bx){
    __syncthreads();
    if (bx == 0){
        if (threadIdx.x < 32){
            __threadfence();
            int lane = threadIdx.x;
            if (lane == 0) st_rel(&g_flags[0], target);
            bool ok;
            do {
                unsigned mn = 0xFFFFFFFFu;
#pragma unroll
                for (int i = 0; i < 4; i++){
                    unsigned v = ld_acq(&g_flags[lane*4 + i]);
                    mn = mn < v ? mn : v;
                }
                ok = __all_sync(0xFFFFFFFFu, mn >= target);
            } while (!ok);
            if (lane == 0) st_rel(&g_epoch, target);
        }
    } else {
        if (threadIdx.x == 0){
            __threadfence();
            st_rel(&g_flags[bx], target);
            while (ld_acq(&g_epoch) < target) {}
        }
    }
    __syncthreads();
}

// cg (L2-coherent) 16B load / 4B store
__device__ __forceinline__ ulonglong2 ldcg2(const float* p){
    longlong2 t = __ldcg((const longlong2*)p);
    ulonglong2 r; r.x = (ull)t.x; r.y = (ull)t.y;
    return r;
}
__device__ __forceinline__ void stcg1(float* p, float v){ __stcg(p, v); }

// ---- classify 'done' wire dtype; also reset barrier state ----
__global__ void detect_kernel(const unsigned* __restrict__ dw){
    __shared__ int s[5];
    if (threadIdx.x < 5) s[threadIdx.x] = 0;
    if (threadIdx.x < NCTA) g_flags[threadIdx.x] = 0;
    __syncthreads();
    int anynz=0, badf=0, badi=0, badb=0, mix=0;
    for (int i = threadIdx.x; i < 16384; i += 256){
        unsigned w = dw[i];
        if (w) anynz = 1;
        if (w != 0u && w != 0x3F800000u) badf = 1;
        if (w > 1u) badi = 1;
        unsigned h0 = w & 0xFFFFu, h1 = w >> 16;
        if ((h0 && h0 != 0x3F80u) || (h1 && h1 != 0x3F80u)) badb = 1;
        if (w == 0x00003F80u || w == 0x3F803F80u) mix = 1;
    }
    if (anynz) atomicOr(&s[0],1);
    if (badf)  atomicOr(&s[1],1);
    if (badi)  atomicOr(&s[2],1);
    if (badb)  atomicOr(&s[3],1);
    if (mix)   atomicOr(&s[4],1);
    __syncthreads();
    if (threadIdx.x == 0){
        int m;
        if (!s[0]) m = 0;
        else if (!s[3] && s[4]) m = 3;
        else if (!s[1]) m = 2;
        else if (!s[2]) m = 1;
        else m = 0;
        g_mode = m; g_epoch = 0;
    }
}

__global__ void convert_kernel(const void* __restrict__ dptr){
    int i = blockIdx.x*256 + threadIdx.x;
    int m = g_mode; int v;
    if (m == 0)      v = ((const unsigned char*) dptr)[i] != 0;
    else if (m == 1) v = ((const int*)           dptr)[i] != 0;
    else if (m == 2) v = ((const float*)         dptr)[i] != 0.0f;
    else             v = ((const unsigned short*)dptr)[i] != 0;
    g_nd[i] = v ? 0.0f : 1.0f;
}

// Fold-exchange: halve the live accumulator set while butterflying lanes.
__device__ __forceinline__ float foldx(float x, float y, bool hi, int off){
    float mine = hi ? y : x;
    float send = hi ? x : y;
    return mine + __shfl_xor_sync(0xFFFFFFFFu, send, off);
}

// --------- one K-half of one LSTM layer over this warp's 16 rows ----------
// Warp covers all 8 unit-gates for K-half `whalf` (x-part or h-part).
// lane l covers k-quads [4l,4l+4) and [128+4l,128+4l+4) within the half.
// Partial gate sums are deposited into sp[row][ug][whalf].
template<bool MASK>
__device__ __forceinline__ void row_phase(
    const float* __restrict__ wsl,   // ws[layer]: [8][512]
    const float* __restrict__ act,   // [128][256] activations for this half
    const float* __restrict__ nd,    // [128] not-done mask (MASK only)
    float* __restrict__ sp,          // [128][8][2]
    int lane, int pair, int whalf)
{
    ulonglong2 W[8][2];              // 64 regs
#pragma unroll
    for (int ug = 0; ug < 8; ug++){
        const float* wp = wsl + ug*512 + whalf*256 + 4*lane;
        W[ug][0] = *(const ulonglong2*)(wp);
        W[ug][1] = *(const ulonglong2*)(wp + 128);
    }
    const bool h16 = (lane & 16) != 0;
    const bool h8  = (lane & 8)  != 0;
    const bool h4  = (lane & 4)  != 0;
    const bool wlane = (lane & 3) == 0;
    const int  ug_w = ((lane >> 4) & 1)*4 + ((lane >> 2) & 3);
    const ull z = 0ull;

#pragma unroll 4
    for (int r = 0; r < 16; r++){
        const int row = pair*16 + r;
        const float* p = act + row*256 + 4*lane;
        ulonglong2 a0 = ldcg2(p);
        ulonglong2 a1 = ldcg2(p + 128);
        if (MASK){
            const ull m2 = pack2(nd[row], nd[row]);
            a0.x = ffma2(a0.x, m2, z);
            a0.y = ffma2(a0.y, m2, z);
            a1.x = ffma2(a1.x, m2, z);
            a1.y = ffma2(a1.y, m2, z);
        }
        float v[8];
#pragma unroll
        for (int ug = 0; ug < 8; ug++){
            ull a;
            a = ffma2(a0.x, W[ug][0].x, z);
            a = ffma2(a0.y, W[ug][0].y, a);
            a = ffma2(a1.x, W[ug][1].x, a);
            a = ffma2(a1.y, W[ug][1].y, a);
            v[ug] = hsum2(a);
        }
        float t0 = foldx(v[0], v[4], h16, 16);
        float t1 = foldx(v[1], v[5], h16, 16);
        float t2 = foldx(v[2], v[6], h16, 16);
        float t3 = foldx(v[3], v[7], h16, 16);
        float p0 = foldx(t0, t2, h8, 8);
        float p1 = foldx(t1, t3, h8, 8);
        float rr = foldx(p0, p1, h4, 4);
        rr += __shfl_xor_sync(0xFFFFFFFFu, rr, 2);
        rr += __shfl_xor_sync(0xFFFFFFFFu, rr, 1);
        if (wlane) sp[row*16 + ug_w*2 + whalf] = rr;
    }
}

__global__ void __launch_bounds__(512,1) scan_kernel(
    const float* __restrict__ x,   const float* __restrict__ h0in,
    const float* __restrict__ c0in,
    const float* __restrict__ wih, const float* __restrict__ whh,
    const float* __restrict__ bih, const float* __restrict__ bhh,
    float* __restrict__ out)
{
    __shared__ __align__(16) float ws[2][8][512];   // [layer][u*4+g][k] x:0..255 h:256..511
    __shared__ __align__(16) float sp[128*16];      // [row][ug][half] partial sums (8KB)
    __shared__ float bs[2][8];
    const int tid = threadIdx.x, bx = blockIdx.x;
    const int lane = tid & 31, w = tid >> 5;
    const int pair = w & 7, whalf = w >> 3;

    for (int i = tid; i < 8192; i += 512){
        int l = i >> 12, rr = i & 4095, ug = rr >> 9, k = rr & 511;
        int uu = ug >> 2, g = ug & 3;
        int row = g*256 + bx*2 + uu;
        float v = (k < 256) ? wih[((l<<10)+row)*256 + k] : whh[((l<<10)+row)*256 + k - 256];
        ws[l][ug][k] = v;
    }
    if (tid < 16){
        int l = tid >> 3, ug = tid & 7, uu = ug >> 2, g = ug & 3;
        int row = g*256 + bx*2 + uu;
        bs[l][ug] = bih[(l<<10)+row] + bhh[(l<<10)+row];
    }
    // owner state: thread tid<256 owns (row = tid>>1, unit = tid&1)
    const int orow = tid >> 1, ou = tid & 1;
    const int oj = bx*2 + ou;
    float c0own = 0.0f, c1own = 0.0f, h0own = 0.0f, h1own = 0.0f;
    if (tid < 256){
        stcg1(&g_h0buf[0][orow*256 + oj], h0in[orow*256 + oj]);
        c0own = c0in[orow*256 + oj];
        c1own = c0in[BH + orow*256 + oj];
    }
    gsync(1, bx);

    int pp = 0;
    for (int t = 0; t < TT; t++){
        const float* nd = g_nd + t*BB;
        // ---- layer 0: x-half reads x(t); h-half reads masked h0(t-1) ----
        if (whalf == 0) row_phase<false>(&ws[0][0][0], x + (size_t)t*BH, nd, sp, lane, pair, 0);
        else            row_phase<true >(&ws[0][0][0], g_h0buf[pp],      nd, sp, lane, pair, 1);
        __syncthreads();
        if (tid < 256){
            float4 A = *(const float4*)&sp[tid*8];
            float4 B = *(const float4*)&sp[tid*8 + 4];
            float m = nd[orow];
            float gi = A.x + A.y + bs[0][ou*4+0];
            float gf = A.z + A.w + bs[0][ou*4+1];
            float gg = B.x + B.y + bs[0][ou*4+2];
            float go = B.z + B.w + bs[0][ou*4+3];
            c0own = sigf(gf)*(c0own*m) + sigf(gi)*tanhe(gg);
            h0own = sigf(go)*tanhe(c0own);
            stcg1(&g_h0buf[pp^1][orow*256 + oj], h0own);
        }
        gsync((unsigned)(t + 2), bx);
        // prefetch x(t+1) into L2 (8 lines/CTA; 1024 chip-wide)
        if (t + 1 < TT && tid < 8){
            const char* nx = (const char*)(x + (size_t)(t+1)*BH) + (size_t)(bx*8 + tid)*128;
            asm volatile("prefetch.global.L2 [%0];" :: "l"(nx));
        }
        // ---- layer 1: x-half reads h0(t); h-half reads masked h1(t-1) ----
        const float* h1src = t ? (g_core + (size_t)(t-1)*BH) : (h0in + BH);
        if (whalf == 0) row_phase<false>(&ws[1][0][0], g_h0buf[pp^1], nd, sp, lane, pair, 0);
        else            row_phase<true >(&ws[1][0][0], h1src,         nd, sp, lane, pair, 1);
        __syncthreads();
        if (tid < 256){
            float4 A = *(const float4*)&sp[tid*8];
            float4 B = *(const float4*)&sp[tid*8 + 4];
            float m = nd[orow];
            float gi = A.x + A.y + bs[1][ou*4+0];
            float gf = A.z + A.w + bs[1][ou*4+1];
            float gg = B.x + B.y + bs[1][ou*4+2];
            float go = B.z + B.w + bs[1][ou*4+3];
            c1own = sigf(gf)*(c1own*m) + sigf(gi)*tanhe(gg);
            h1own = sigf(go)*tanhe(c1own);
            stcg1(&g_core[(size_t)t*BH + orow*256 + oj], h1own);
        }
        __syncthreads();   // protect sp before next step's row_phase writes
        pp ^= 1;
    }
    if (tid < 256){
        out[OFF_HT +      orow*256 + oj] = h0own;
        out[OFF_HT + BH + orow*256 + oj] = h1own;
        out[OFF_CT +      orow*256 + oj] = c0own;
        out[OFF_CT + BH + orow*256 + oj] = c1own;
    }
}

__global__ void __launch_bounds__(256) head_kernel(
    const float* __restrict__ Wp, const float* __restrict__ bp,
    const float* __restrict__ Wb, const float* __restrict__ bb,
    float* __restrict__ out)
{
    __shared__ float sw[19*256];
    for (int i = threadIdx.x; i < 19*256; i += 256)
        sw[i] = (i < 18*256) ? Wp[i] : Wb[i - 18*256];
    __syncthreads();
    int warp = (blockIdx.x*blockDim.x + threadIdx.x) >> 5;
    int lane = threadIdx.x & 31;
    if (warp >= TT*BB) return;
    const float* cr = g_core + (size_t)warp*256;
    float acc[19];
#pragma unroll
    for (int a = 0; a < 19; a++) acc[a] = 0.0f;
#pragma unroll
    for (int k0 = 0; k0 < 8; k0++){
        float v = cr[k0*32 + lane];
#pragma unroll
        for (int a = 0; a < 19; a++) acc[a] += v * sw[a*256 + k0*32 + lane];
    }
#pragma unroll
    for (int a = 0; a < 19; a++)
        for (int o = 16; o > 0; o >>= 1) acc[a] += __shfl_xor_sync(0xFFFFFFFFu, acc[a], o);
    if (lane == 0){
        float best = -3.0e38f; int bi = 0;
        for (int a = 0; a < 18; a++){
            float lg = acc[a] + bp[a];
            out[(size_t)warp*AA + a] = lg;
            if (lg > best){ best = lg; bi = a; }
        }
        out[OFF_BASE + warp] = acc[18] + bb[0];
        out[OFF_ACT  + warp] = (float)bi;
    }
}

extern "C" void kernel_launch(void* const* d_in, const int* in_sizes, int n_in,
                              void* d_out, int out_size){
    const float* x    = (const float*)d_in[0];
    const void*  done = d_in[1];
    const float* h0   = (const float*)d_in[2];
    const float* c0   = (const float*)d_in[3];
    const float* wih  = (const float*)d_in[4];
    const float* whh  = (const float*)d_in[5];
    const float* bih  = (const float*)d_in[6];
    const float* bhh  = (const float*)d_in[7];
    const float* Wp   = (const float*)d_in[8];
    const float* bp   = (const float*)d_in[9];
    const float* Wb   = (const float*)d_in[10];
    const float* bb   = (const float*)d_in[11];
    float* out = (float*)d_out;

    detect_kernel<<<1, 256>>>((const unsigned*)done);
    convert_kernel<<<256, 256>>>(done);
    scan_kernel<<<NCTA, 512>>>(x, h0, c0, wih, whh, bih, bhh, out);
    head_kernel<<<8192, 256>>>(Wp, bp, Wb, bb, out);
}